// round 15
// baseline (speedup 1.0000x reference)
#include <cuda_runtime.h>
#include <cuda_fp16.h>
#include <math.h>
#include <stdint.h>

#define Bc 4
#define Sc 2048
#define Ec 768
#define Hc 12
#define Dc 64
#define E3 2304
#define NGLOB 204

// Scratch (device globals; no runtime allocation allowed)
__device__ __half g_qkvh[(size_t)Bc * Sc * E3];    // Q,K natural (V region unused)
__device__ __half g_attnh[(size_t)Bc * Sc * Ec];
__device__ __half g_xh[(size_t)Bc * Sc * Ec];
__device__ __half g_waT[(size_t)E3 * Ec];
__device__ __half g_wpT[(size_t)Ec * Ec];
__device__ __half g_vTh[(size_t)Bc * Hc * Dc * Sc];
__device__ __half g_Kgh[16 * 256 * 64];
__device__ __half g_VgTh[16 * 64 * 256];
__device__ int    g_gjpad[256];
__device__ int    g_gstart[32];

// ---------------------------------------------------------------------------
__device__ __forceinline__ void mma_f16(float* d, const unsigned* a, unsigned b0, unsigned b1) {
    asm volatile(
        "mma.sync.aligned.m16n8k16.row.col.f32.f16.f16.f32 "
        "{%0,%1,%2,%3}, {%4,%5,%6,%7}, {%8,%9}, {%0,%1,%2,%3};"
        : "+f"(d[0]), "+f"(d[1]), "+f"(d[2]), "+f"(d[3])
        : "r"(a[0]), "r"(a[1]), "r"(a[2]), "r"(a[3]), "r"(b0), "r"(b1));
}
__device__ __forceinline__ void ldsm4(unsigned& r0, unsigned& r1, unsigned& r2, unsigned& r3,
                                      uint32_t addr) {
    asm volatile("ldmatrix.sync.aligned.m8n8.x4.shared.b16 {%0,%1,%2,%3}, [%4];"
                 : "=r"(r0), "=r"(r1), "=r"(r2), "=r"(r3) : "r"(addr));
}
__device__ __forceinline__ uint32_t smem_u32(const void* p) {
    uint32_t a;
    asm("{ .reg .u64 t; cvta.to.shared.u64 t, %1; cvt.u32.u64 %0, t; }" : "=r"(a) : "l"(p));
    return a;
}
__device__ __forceinline__ void cpa16(uint32_t dst, const void* src) {
    asm volatile("cp.async.cg.shared.global [%0], [%1], 16;" :: "r"(dst), "l"(src));
}
__device__ __forceinline__ void cpa_commit() {
    asm volatile("cp.async.commit_group;" ::: "memory");
}
__device__ __forceinline__ unsigned h2mul(unsigned v, unsigned sc) {
    __half2 a = __hmul2(*(__half2*)&v, *(__half2*)&sc);
    return *(unsigned*)&a;
}
__device__ __forceinline__ unsigned packh2(float lo, float hi) {
    __half2 h = __floats2half2_rn(lo, hi);
    return *(unsigned*)&h;
}
__device__ __forceinline__ unsigned ex2h2(unsigned v) {
    unsigned r;
    asm("ex2.approx.f16x2 %0, %1;" : "=r"(r) : "r"(v));
    return r;
}
#define ONES_H2 0x3C003C00u
#define MASKV  (-30000.0f)

// ---------------------------------------------------------------------------
// Fused prep: blk 0 = gpos, next CVTH_BLKS = x->half, then waT, then wpT.
// ---------------------------------------------------------------------------
#define CVTH_N4    ((Bc * Sc * Ec) / 4)
#define CVTH_BLKS  (CVTH_N4 / 256)
#define WAT_BX     (E3 / 32)
#define WAT_BLKS   (WAT_BX * (Ec / 32))
#define WPT_BX     (Ec / 32)
#define WPT_BLKS   (WPT_BX * (Ec / 32))
#define PREP_BLKS  (1 + CVTH_BLKS + WAT_BLKS + WPT_BLKS)

__global__ __launch_bounds__(256) void prep_kernel(
    const float* __restrict__ x, const float* __restrict__ w_attn,
    const float* __restrict__ w_proj)
{
    __shared__ float t[32][33];
    const int blk = blockIdx.x;
    const int tid = threadIdx.x;

    if (blk == 0) {
        const float step = (float)((double)(Sc - 1) / (double)(NGLOB - 1));
        int j = -1;
        if (tid < NGLOB) {
            if (tid == NGLOB - 1) j = Sc - 1;
            else                  j = (int)(__fmul_rn((float)tid, step));
            if (j < 0) j = 0;
            if (j > Sc - 1) j = Sc - 1;
        }
        g_gjpad[tid] = j;
        __syncthreads();
        if (tid < 32) {
            int q0 = tid * 64, cnt = 0;
            for (int k = 0; k < NGLOB; k++) cnt += (g_gjpad[k] <= q0) ? 1 : 0;
            g_gstart[tid] = cnt;
        }
        return;
    }
    if (blk <= CVTH_BLKS) {
        int i = (blk - 1) * 256 + tid;
        float4 v = ((const float4*)x)[i];
        __half2 h0 = __floats2half2_rn(v.x, v.y);
        __half2 h1 = __floats2half2_rn(v.z, v.w);
        uint2 u;
        u.x = *(unsigned*)&h0;
        u.y = *(unsigned*)&h1;
        ((uint2*)g_xh)[i] = u;
        return;
    }
    const float* W;
    __half* WT;
    int bx, by, K, N;
    if (blk <= CVTH_BLKS + WAT_BLKS) {
        int bid = blk - 1 - CVTH_BLKS;
        W = w_attn; WT = g_waT; K = Ec; N = E3;
        bx = bid % WAT_BX; by = bid / WAT_BX;
    } else {
        int bid = blk - 1 - CVTH_BLKS - WAT_BLKS;
        W = w_proj; WT = g_wpT; K = Ec; N = Ec;
        bx = bid % WPT_BX; by = bid / WPT_BX;
    }
    int n0 = bx * 32, k0 = by * 32;
    int tx = tid & 31, ty = tid >> 5;
#pragma unroll
    for (int i = 0; i < 4; i++)
        t[ty + i * 8][tx] = W[(size_t)(k0 + ty + i * 8) * N + n0 + tx];
    __syncthreads();
#pragma unroll
    for (int i = 0; i < 4; i++)
        WT[(size_t)(n0 + ty + i * 8) * K + k0 + tx] = __float2half(t[tx][ty + i * 8]);
}

// ---------------------------------------------------------------------------
// Gather-only kernel: compact global K from qkvh (natural), V from g_vTh.
// ---------------------------------------------------------------------------
__global__ __launch_bounds__(256) void gather_kernel(const __half* __restrict__ qkv,
                                                     const __half* __restrict__ vT) {
    const int tid = threadIdx.x;
    int bhg = blockIdx.x >> 2;
    int q = blockIdx.x & 3;
    int b = bhg >> 2, h = 8 + (bhg & 3);
    int s0 = q * 64;
    const __half* kb = qkv + (size_t)b * Sc * E3 + Ec + h * Dc;
    const __half* vr = vT + (size_t)(b * Hc + h) * Dc * Sc;
    __half* Kg = g_Kgh + (size_t)bhg * 256 * 64;
    __half* VgT = g_VgTh + (size_t)bhg * 64 * 256;
    uint4 z = make_uint4(0u, 0u, 0u, 0u);

#pragma unroll
    for (int i = 0; i < 2; i++) {
        int idx = tid + i * 256;
        int sl = idx >> 3, c16 = idx & 7;
        int j = g_gjpad[s0 + sl];
        uint4 kv = (j >= 0) ? *(const uint4*)(kb + (size_t)j * E3 + c16 * 8) : z;
        *(uint4*)(Kg + (size_t)(s0 + sl) * 64 + c16 * 8) = kv;
    }
#pragma unroll
    for (int i = 0; i < 2; i++) {
        int idx = tid + i * 256;
        int d = idx >> 3, sl8 = (idx & 7) * 8;
        uint4 u;
        unsigned short* us = (unsigned short*)&u;
        const __half* vrow = vr + (size_t)d * Sc;
#pragma unroll
        for (int k = 0; k < 8; k++) {
            int j = g_gjpad[s0 + sl8 + k];
            __half val = (j >= 0) ? vrow[j] : __ushort_as_half((unsigned short)0);
            us[k] = *(const unsigned short*)&val;
        }
        *(uint4*)(VgT + (size_t)d * 256 + s0 + sl8) = u;
    }
}

// ---------------------------------------------------------------------------
// fp16 GEMM (m16n8k16), 128x256 tile, 512 threads (16 warps 4m x 4n),
// 3-stage cp.async pipeline + ldmatrix.
// vmode=1 (QKV, N=2304 in 256-col tiles): bx<6 -> Q/K natural fp16; bx>=6 ->
// V transposed into vTp via smem staging. vmode=0 (proj): f32 output.
// ---------------------------------------------------------------------------
#define HST_BYTES 30720      // A 128*80 + B 256*80
#define HST_BOFF  10240
#define HGS_TOTAL (3 * HST_BYTES)

__device__ __forceinline__ void copy_stage_h(const __half* __restrict__ A, const __half* __restrict__ WT,
                                             int m0, int n0, int K, int kt,
                                             uint32_t sbase, int tid) {
    const int kb = kt * 32;
    const uint32_t sA = sbase, sB = sbase + HST_BOFF;
    {
        int row = tid >> 2, ch = tid & 3;     // 512 = 128 rows x 4 chunks
        cpa16(sA + row * 80 + ch * 16, A + (size_t)(m0 + row) * K + kb + ch * 8);
    }
#pragma unroll
    for (int i = 0; i < 2; i++) {
        int idx = tid + i * 512;              // 1024 = 256 rows x 4 chunks
        int row = idx >> 2, ch = idx & 3;
        cpa16(sB + row * 80 + ch * 16, WT + (size_t)(n0 + row) * K + kb + ch * 8);
    }
    cpa_commit();
}

__global__ __launch_bounds__(512, 1) void gemm_f16(
    const __half* __restrict__ A, const __half* __restrict__ WT,
    const float* __restrict__ bias, float* __restrict__ Cf, __half* __restrict__ Ch,
    __half* __restrict__ vTp, int M, int N, int K, int vmode)
{
    extern __shared__ char smem[];
    const uint32_t sb = smem_u32(smem);

    const int tid = threadIdx.x;
    const int lane = tid & 31;
    const int w = tid >> 5;                  // 0..15
    const int g = lane >> 2, c = lane & 3;
    const int wm = (w & 3) * 32;
    const int wn = (w >> 2) * 64;            // 0..192
    const int m0 = blockIdx.y << 7, n0 = blockIdx.x << 8;
    const int NT = K >> 5;

    uint32_t aOff[2], bOff[4];
#pragma unroll
    for (int mt = 0; mt < 2; mt++)
        aOff[mt] = (uint32_t)(wm + mt * 16 + (lane & 15)) * 80 + ((lane >> 4) ? 16u : 0u);
#pragma unroll
    for (int p = 0; p < 4; p++)
        bOff[p] = HST_BOFF +
                  (uint32_t)(wn + 16 * p + ((lane >> 4) & 1) * 8 + (lane & 7)) * 80 +
                  ((lane >> 3) & 1) * 16;

    float acc[2][8][4];
#pragma unroll
    for (int mt = 0; mt < 2; mt++)
#pragma unroll
        for (int nt = 0; nt < 8; nt++)
#pragma unroll
            for (int i = 0; i < 4; i++) acc[mt][nt][i] = 0.f;

    copy_stage_h(A, WT, m0, n0, K, 0, sb, tid);
    copy_stage_h(A, WT, m0, n0, K, 1, sb + HST_BYTES, tid);
    copy_stage_h(A, WT, m0, n0, K, 2, sb + 2 * HST_BYTES, tid);

    for (int kt = 0; kt < NT; kt++) {
        asm volatile("cp.async.wait_group 2;" ::: "memory");
        __syncthreads();

        const uint32_t stg = sb + (kt % 3) * HST_BYTES;
#pragma unroll
        for (int ks = 0; ks < 2; ks++) {
            const uint32_t ko = ks * 32;
            unsigned a[2][4];
            ldsm4(a[0][0], a[0][1], a[0][2], a[0][3], stg + aOff[0] + ko);
            ldsm4(a[1][0], a[1][1], a[1][2], a[1][3], stg + aOff[1] + ko);
#pragma unroll
            for (int p = 0; p < 4; p++) {
                unsigned b0, b1, b2, b3;
                ldsm4(b0, b1, b2, b3, stg + bOff[p] + ko);
                mma_f16(acc[0][2 * p], a[0], b0, b1);
                mma_f16(acc[1][2 * p], a[1], b0, b1);
                mma_f16(acc[0][2 * p + 1], a[0], b2, b3);
                mma_f16(acc[1][2 * p + 1], a[1], b2, b3);
            }
        }
        __syncthreads();

        if (kt + 3 < NT) copy_stage_h(A, WT, m0, n0, K, kt + 3, sb + (kt % 3) * HST_BYTES, tid);
        else             cpa_commit();
    }

    if (vmode && blockIdx.x >= 6) {
        // V tile (256 cols): stage transposed in smem [col][136], coalesced vT write
        asm volatile("cp.async.wait_group 0;" ::: "memory");
        __syncthreads();
        __half* st = (__half*)smem;        // [256][136]
#pragma unroll
        for (int mt = 0; mt < 2; mt++) {
            int r = wm + mt * 16 + g;
#pragma unroll
            for (int nt = 0; nt < 8; nt++) {
                int col = wn + nt * 8 + 2 * c;
                float bv0 = bias[n0 + col], bv1 = bias[n0 + col + 1];
                st[col * 136 + r]             = __float2half(acc[mt][nt][0] + bv0);
                st[(col + 1) * 136 + r]       = __float2half(acc[mt][nt][1] + bv1);
                st[col * 136 + r + 8]         = __float2half(acc[mt][nt][2] + bv0);
                st[(col + 1) * 136 + r + 8]   = __float2half(acc[mt][nt][3] + bv1);
            }
        }
        __syncthreads();
        const int b = m0 >> 11, s0r = m0 & (Sc - 1);
#pragma unroll
        for (int i = 0; i < 8; i++) {
            int idx = tid + i * 512;
            int col = idx >> 4, seg = (idx & 15) * 8;
            int colg = n0 + col - 2 * Ec;     // offset within V region [0, Ec)
            int h = colg >> 6, d = colg & 63;
            uint4 u;
            unsigned short* us = (unsigned short*)&u;
            const unsigned short* srow = (const unsigned short*)(st + col * 136 + seg);
#pragma unroll
            for (int j = 0; j < 8; j++) us[j] = srow[j];
            *(uint4*)(vTp + ((size_t)(b * Hc + h) * Dc + d) * Sc + s0r + seg) = u;
        }
        return;
    }

#pragma unroll
    for (int mt = 0; mt < 2; mt++) {
        int r0 = m0 + wm + mt * 16 + g;
#pragma unroll
        for (int nt = 0; nt < 8; nt++) {
            int col = n0 + wn + nt * 8 + 2 * c;
            float bv0 = bias[col], bv1 = bias[col + 1];
            float v00 = acc[mt][nt][0] + bv0, v01 = acc[mt][nt][1] + bv1;
            float v10 = acc[mt][nt][2] + bv0, v11 = acc[mt][nt][3] + bv1;
            if (vmode) {
                *(__half2*)(Ch + (size_t)r0 * N + col) = __floats2half2_rn(v00, v01);
                *(__half2*)(Ch + (size_t)(r0 + 8) * N + col) = __floats2half2_rn(v10, v11);
            } else {
                *(float2*)(Cf + (size_t)r0 * N + col) = make_float2(v00, v01);
                *(float2*)(Cf + (size_t)(r0 + 8) * N + col) = make_float2(v10, v11);
            }
        }
    }
}

// ---------------------------------------------------------------------------
// fp16 attention (R14): 64 q-rows, 128 threads, log2-domain + ex2.f16x2,
// l via ones-mma, mask fast-paths, LPT grid, ldmatrix, 2-stage cp.async.
// ---------------------------------------------------------------------------
#define AST_BYTES 18432
#define AST_VOFF  9216
#define ATT_TOTAL (2 * AST_BYTES)

__device__ __forceinline__ void attn_issue(
    int it, int n_causal, int n_tiles, int kt_base, int ct0,
    const __half* __restrict__ kb, const __half* __restrict__ vTb,
    const __half* __restrict__ KgB, const __half* __restrict__ VgTB,
    uint32_t sbase, int tid)
{
    if (it >= n_tiles) { cpa_commit(); return; }
    const uint32_t sK = sbase, sV = sbase + AST_VOFF;
    if (it < n_causal) {
        const int k0 = (kt_base + it) << 6;
#pragma unroll
        for (int i = 0; i < 4; i++) {
            int idx = tid + i * 128;
            int slot = idx >> 3, c16 = idx & 7;
            cpa16(sK + slot * 144 + c16 * 16, kb + (size_t)(k0 + slot) * E3 + c16 * 8);
            cpa16(sV + slot * 144 + c16 * 16, vTb + (size_t)slot * Sc + k0 + c16 * 8);
        }
    } else {
        const int ct = ct0 + it - n_causal;
        const __half* Kt = KgB + (size_t)ct * 64 * 64;
#pragma unroll
        for (int i = 0; i < 4; i++) {
            int idx = tid + i * 128;
            int slot = idx >> 3, c16 = idx & 7;
            cpa16(sK + slot * 144 + c16 * 16, Kt + (size_t)slot * 64 + c16 * 8);
            cpa16(sV + slot * 144 + c16 * 16, VgTB + (size_t)slot * 256 + ct * 64 + c16 * 8);
        }
    }
    cpa_commit();
}

__global__ __launch_bounds__(128) void attn_tc(
    const __half* __restrict__ qkv, __half* __restrict__ out, int half_w)
{
    extern __shared__ char smem[];
    const uint32_t sb = smem_u32(smem);

    const int bid = blockIdx.x;
    int b, h, qt;
    if (bid < 512) {
        h = 8 + (bid & 3);
        qt = 31 - ((bid >> 2) & 31);
        b = bid >> 7;
    } else {
        int l = bid - 512;
        h = l & 7;
        qt = 31 - ((l >> 3) & 31);
        b = l >> 8;
    }
    const bool is_local = (h < 8);
    const int q0 = qt << 6;
    const int tid = threadIdx.x;
    const int lane = tid & 31;
    const int w = tid >> 5;
    const int g = lane >> 2, c = lane & 3;

    const __half* qb = qkv + (size_t)b * Sc * E3 + h * Dc;
    const __half* kb = qb + Ec;
    const __half* vTb = g_vTh + (size_t)(b * Hc + h) * Dc * Sc;
    const __half* KgB = g_Kgh + (size_t)(b * 4 + (h - 8)) * 256 * 64;
    const __half* VgTB = g_VgTh + (size_t)(b * 4 + (h - 8)) * 64 * 256;

    const int r0 = q0 + 16 * w + g;
    const int r1 = r0 + 8;

    uint32_t kOff[4], vOff[4];
#pragma unroll
    for (int p = 0; p < 4; p++) {
        uint32_t row = 16 * p + ((lane >> 4) & 1) * 8 + (lane & 7);
        uint32_t co = ((lane >> 3) & 1) * 16;
        kOff[p] = row * 144 + co;
        vOff[p] = AST_VOFF + row * 144 + co;
    }

    __half2 qsch = __half2half2(__float2half(0.18033688f));
    const unsigned qsc = *(unsigned*)&qsch;
    const unsigned* qw0 = (const unsigned*)(qb + (size_t)r0 * E3);
    const unsigned* qw1 = (const unsigned*)(qb + (size_t)r1 * E3);
    unsigned qa[4][4];
#pragma unroll
    for (int ks = 0; ks < 4; ks++) {
        qa[ks][0] = h2mul(qw0[8 * ks + c], qsc);
        qa[ks][1] = h2mul(qw1[8 * ks + c], qsc);
        qa[ks][2] = h2mul(qw0[8 * ks + 4 + c], qsc);
        qa[ks][3] = h2mul(qw1[8 * ks + 4 + c], qsc);
    }

    float o[8][4];
#pragma unroll
    for (int nt = 0; nt < 8; nt++)
#pragma unroll
        for (int i = 0; i < 4; i++) o[nt][i] = 0.f;
    float lacc[4] = {0.f, 0.f, 0.f, 0.f};

    int kt_base, n_causal, n_tiles, ct0 = 0;
    if (is_local) {
        int lo = (q0 - half_w) >> 6;
        kt_base = lo > 0 ? lo : 0;
        n_causal = qt - kt_base + 1;
        n_tiles = n_causal;
    } else {
        kt_base = 0;
        n_causal = qt + 1;
        ct0 = g_gstart[qt] >> 6;
        n_tiles = n_causal + (4 - ct0);
    }

    attn_issue(0, n_causal, n_tiles, kt_base, ct0, kb, vTb, KgB, VgTB, sb, tid);
    attn_issue(1, n_causal, n_tiles, kt_base, ct0, kb, vTb, KgB, VgTB, sb + AST_BYTES, tid);

    for (int it = 0; it < n_tiles; it++) {
        asm volatile("cp.async.wait_group 1;" ::: "memory");
        __syncthreads();

        const uint32_t stg = sb + (it & 1) * AST_BYTES;
        const bool compact = (!is_local) && (it >= n_causal);
        const int kt = kt_base + it;
        const int k0 = kt << 6;
        const int ctb = compact ? (ct0 + it - n_causal) * 64 : 0;

        float s[8][4];
#pragma unroll
        for (int nt = 0; nt < 8; nt++)
#pragma unroll
            for (int i = 0; i < 4; i++) s[nt][i] = 0.f;
#pragma unroll
        for (int ks = 0; ks < 4; ks++) {
            const uint32_t ko = ks * 32;
#pragma unroll
            for (int p = 0; p < 4; p++) {
                unsigned k0f, k1f, k2f, k3f;
                ldsm4(k0f, k1f, k2f, k3f, stg + kOff[p] + ko);
                mma_f16(s[2 * p], qa[ks], k0f, k1f);
                mma_f16(s[2 * p + 1], qa[ks], k2f, k3f);
            }
        }

        int mode = compact ? 3
                 : (kt == qt ? 1
                 : ((is_local && k0 < q0 + 64 - half_w) ? 2 : 0));
        if (mode == 1) {
#pragma unroll
            for (int nt = 0; nt < 8; nt++) {
                int jA = k0 + 8 * nt + 2 * c, jB = jA + 1;
                s[nt][0] = (jA <= r0) ? s[nt][0] : MASKV;
                s[nt][1] = (jB <= r0) ? s[nt][1] : MASKV;
                s[nt][2] = (jA <= r1) ? s[nt][2] : MASKV;
                s[nt][3] = (jB <= r1) ? s[nt][3] : MASKV;
            }
        } else if (mode == 2) {
#pragma unroll
            for (int nt = 0; nt < 8; nt++) {
                int jA = k0 + 8 * nt + 2 * c, jB = jA + 1;
                s[nt][0] = (jA >= r0 - half_w) ? s[nt][0] : MASKV;
                s[nt][1] = (jB >= r0 - half_w) ? s[nt][1] : MASKV;
                s[nt][2] = (jA >= r1 - half_w) ? s[nt][2] : MASKV;
                s[nt][3] = (jB >= r1 - half_w) ? s[nt][3] : MASKV;
            }
        } else if (mode == 3) {
#pragma unroll
            for (int nt = 0; nt < 8; nt++) {
                int jA = g_gjpad[ctb + 8 * nt + 2 * c];
                int jB = g_gjpad[ctb + 8 * nt + 2 * c + 1];
                s[nt][0] = (jA > r0) ? s[nt][0] : MASKV;
                s[nt][1] = (jB > r0) ? s[nt][1] : MASKV;
                s[nt][2] = (jA > r1) ? s[nt][2] : MASKV;
                s[nt][3] = (jB > r1) ? s[nt][3] : MASKV;
            }
        }

        unsigned p01[8], p23[8];
#pragma unroll
        for (int nt = 0; nt < 8; nt++) {
            p01[nt] = ex2h2(packh2(s[nt][0], s[nt][1]));
            p23[nt] = ex2h2(packh2(s[nt][2], s[nt][3]));
        }

#pragma unroll
        for (int t2 = 0; t2 < 4; t2++) {
            unsigned pa[4];
            pa[0] = p01[2 * t2];
            pa[1] = p23[2 * t2];
            pa[2] = p01[2 * t2 + 1];
            pa[3] = p23[2 * t2 + 1];
            mma_f16(lacc, pa, ONES_H2, ONES_H2);
            const uint32_t ko = t2 * 32;
#pragma unroll
            for (int p = 0; p < 4; p++) {
                unsigned v0, v1, v2, v3;
                ldsm4(v0, v1, v2, v3, stg + vOff[p] + ko);
                mma_f16(o[2 * p], pa, v0, v1);
                mma_f16(o[2 * p + 1], pa, v2, v3);
            }
        }
        __syncthreads();

        attn_issue(it + 2, n_causal, n_tiles, kt_base, ct0, kb, vTb, KgB, VgTB,
                   sb + (it & 1) * AST_BYTES, tid);
    }

    float inv0 = 1.0f / lacc[0], inv1 = 1.0f / lacc[2];
    __half* ob0 = out + (size_t)(b * Sc + r0) * Ec + h * Dc;
    __half* ob1 = out + (size_t)(b * Sc + r1) * Ec + h * Dc;
#pragma unroll
    for (int nt = 0; nt < 8; nt++) {
        int d = 8 * nt + 2 * c;
        *(__half2*)(ob0 + d) = __floats2half2_rn(o[nt][0] * inv0, o[nt][1] * inv0);
        *(__half2*)(ob1 + d) = __floats2half2_rn(o[nt][2] * inv1, o[nt][3] * inv1);
    }
}

// ---------------------------------------------------------------------------
extern "C" void kernel_launch(void* const* d_in, const int* in_sizes, int n_in,
                              void* d_out, int out_size) {
    const float* x      = (const float*)d_in[0];
    const float* w_attn = (const float*)d_in[1];
    const float* b_attn = (const float*)d_in[2];
    const float* w_proj = (const float*)d_in[3];
    const float* b_proj = (const float*)d_in[4];
    float* out = (float*)d_out;

    __half *qkvh_p, *attnh_p, *xh_p, *waT_p, *wpT_p, *vT_p;
    cudaGetSymbolAddress((void**)&qkvh_p, g_qkvh);
    cudaGetSymbolAddress((void**)&attnh_p, g_attnh);
    cudaGetSymbolAddress((void**)&xh_p, g_xh);
    cudaGetSymbolAddress((void**)&waT_p, g_waT);
    cudaGetSymbolAddress((void**)&wpT_p, g_wpT);
    cudaGetSymbolAddress((void**)&vT_p, g_vTh);

    int wdw = (int)(128.0 * sqrt((double)Sc / 128.0));
    if (wdw < 32) wdw = 32;
    if (wdw > 512) wdw = 512;
    int half_w = wdw / 2;

    cudaFuncSetAttribute(gemm_f16, cudaFuncAttributeMaxDynamicSharedMemorySize, HGS_TOTAL);
    cudaFuncSetAttribute(attn_tc, cudaFuncAttributeMaxDynamicSharedMemorySize, ATT_TOTAL);

    prep_kernel<<<PREP_BLKS, 256>>>(x, w_attn, w_proj);

    dim3 g1(E3 / 256, (Bc * Sc) / 128);
    gemm_f16<<<g1, 512, HGS_TOTAL>>>(xh_p, waT_p, b_attn, nullptr, qkvh_p, vT_p,
                                     Bc * Sc, E3, Ec, 1);

    gather_kernel<<<64, 256>>>(qkvh_p, vT_p);

    attn_tc<<<1536, 128, ATT_TOTAL>>>(qkvh_p, attnh_p, half_w);

    dim3 g2(Ec / 256, (Bc * Sc) / 128);
    gemm_f16<<<g2, 512, HGS_TOTAL>>>(attnh_p, wpT_p, b_proj, out, nullptr, nullptr,
                                     Bc * Sc, Ec, Ec, 0);
}

// round 16
// speedup vs baseline: 1.2140x; 1.2140x over previous
#include <cuda_runtime.h>
#include <cuda_fp16.h>
#include <math.h>
#include <stdint.h>

#define Bc 4
#define Sc 2048
#define Ec 768
#define Hc 12
#define Dc 64
#define E3 2304
#define NGLOB 204

// Scratch (device globals; no runtime allocation allowed)
__device__ __half g_qkvh[(size_t)Bc * Sc * E3];    // Q,K natural (V region unused)
__device__ __half g_attnh[(size_t)Bc * Sc * Ec];
__device__ __half g_xh[(size_t)Bc * Sc * Ec];
__device__ __half g_waT[(size_t)E3 * Ec];
__device__ __half g_wpT[(size_t)Ec * Ec];
__device__ __half g_vTh[(size_t)Bc * Hc * Dc * Sc];
__device__ __half g_Kgh[16 * 256 * 64];
__device__ __half g_VgTh[16 * 64 * 256];
__device__ int    g_gjpad[256];
__device__ int    g_gstart[32];

// ---------------------------------------------------------------------------
__device__ __forceinline__ void mma_f16(float* d, const unsigned* a, unsigned b0, unsigned b1) {
    asm volatile(
        "mma.sync.aligned.m16n8k16.row.col.f32.f16.f16.f32 "
        "{%0,%1,%2,%3}, {%4,%5,%6,%7}, {%8,%9}, {%0,%1,%2,%3};"
        : "+f"(d[0]), "+f"(d[1]), "+f"(d[2]), "+f"(d[3])
        : "r"(a[0]), "r"(a[1]), "r"(a[2]), "r"(a[3]), "r"(b0), "r"(b1));
}
__device__ __forceinline__ void ldsm4(unsigned& r0, unsigned& r1, unsigned& r2, unsigned& r3,
                                      uint32_t addr) {
    asm volatile("ldmatrix.sync.aligned.m8n8.x4.shared.b16 {%0,%1,%2,%3}, [%4];"
                 : "=r"(r0), "=r"(r1), "=r"(r2), "=r"(r3) : "r"(addr));
}
__device__ __forceinline__ uint32_t smem_u32(const void* p) {
    uint32_t a;
    asm("{ .reg .u64 t; cvta.to.shared.u64 t, %1; cvt.u32.u64 %0, t; }" : "=r"(a) : "l"(p));
    return a;
}
__device__ __forceinline__ void cpa16(uint32_t dst, const void* src) {
    asm volatile("cp.async.cg.shared.global [%0], [%1], 16;" :: "r"(dst), "l"(src));
}
__device__ __forceinline__ void cpa_commit() {
    asm volatile("cp.async.commit_group;" ::: "memory");
}
__device__ __forceinline__ unsigned h2mul(unsigned v, unsigned sc) {
    __half2 a = __hmul2(*(__half2*)&v, *(__half2*)&sc);
    return *(unsigned*)&a;
}
__device__ __forceinline__ unsigned packh2(float lo, float hi) {
    __half2 h = __floats2half2_rn(lo, hi);
    return *(unsigned*)&h;
}
__device__ __forceinline__ unsigned ex2h2(unsigned v) {
    unsigned r;
    asm("ex2.approx.f16x2 %0, %1;" : "=r"(r) : "r"(v));
    return r;
}
#define ONES_H2 0x3C003C00u
#define MASKV  (-30000.0f)

// ---------------------------------------------------------------------------
// Fused prep: blk 0 = gpos, next CVTH_BLKS = x->half, then waT, then wpT.
// ---------------------------------------------------------------------------
#define CVTH_N4    ((Bc * Sc * Ec) / 4)
#define CVTH_BLKS  (CVTH_N4 / 256)
#define WAT_BX     (E3 / 32)
#define WAT_BLKS   (WAT_BX * (Ec / 32))
#define WPT_BX     (Ec / 32)
#define WPT_BLKS   (WPT_BX * (Ec / 32))
#define PREP_BLKS  (1 + CVTH_BLKS + WAT_BLKS + WPT_BLKS)

__global__ __launch_bounds__(256) void prep_kernel(
    const float* __restrict__ x, const float* __restrict__ w_attn,
    const float* __restrict__ w_proj)
{
    __shared__ float t[32][33];
    const int blk = blockIdx.x;
    const int tid = threadIdx.x;

    if (blk == 0) {
        const float step = (float)((double)(Sc - 1) / (double)(NGLOB - 1));
        int j = -1;
        if (tid < NGLOB) {
            if (tid == NGLOB - 1) j = Sc - 1;
            else                  j = (int)(__fmul_rn((float)tid, step));
            if (j < 0) j = 0;
            if (j > Sc - 1) j = Sc - 1;
        }
        g_gjpad[tid] = j;
        __syncthreads();
        if (tid < 32) {
            int q0 = tid * 64, cnt = 0;
            for (int k = 0; k < NGLOB; k++) cnt += (g_gjpad[k] <= q0) ? 1 : 0;
            g_gstart[tid] = cnt;
        }
        return;
    }
    if (blk <= CVTH_BLKS) {
        int i = (blk - 1) * 256 + tid;
        float4 v = ((const float4*)x)[i];
        __half2 h0 = __floats2half2_rn(v.x, v.y);
        __half2 h1 = __floats2half2_rn(v.z, v.w);
        uint2 u;
        u.x = *(unsigned*)&h0;
        u.y = *(unsigned*)&h1;
        ((uint2*)g_xh)[i] = u;
        return;
    }
    const float* W;
    __half* WT;
    int bx, by, K, N;
    if (blk <= CVTH_BLKS + WAT_BLKS) {
        int bid = blk - 1 - CVTH_BLKS;
        W = w_attn; WT = g_waT; K = Ec; N = E3;
        bx = bid % WAT_BX; by = bid / WAT_BX;
    } else {
        int bid = blk - 1 - CVTH_BLKS - WAT_BLKS;
        W = w_proj; WT = g_wpT; K = Ec; N = Ec;
        bx = bid % WPT_BX; by = bid / WPT_BX;
    }
    int n0 = bx * 32, k0 = by * 32;
    int tx = tid & 31, ty = tid >> 5;
#pragma unroll
    for (int i = 0; i < 4; i++)
        t[ty + i * 8][tx] = W[(size_t)(k0 + ty + i * 8) * N + n0 + tx];
    __syncthreads();
#pragma unroll
    for (int i = 0; i < 4; i++)
        WT[(size_t)(n0 + ty + i * 8) * K + k0 + tx] = __float2half(t[tx][ty + i * 8]);
}

// ---------------------------------------------------------------------------
// Gather-only kernel: compact global K from qkvh (natural), V from g_vTh.
// ---------------------------------------------------------------------------
__global__ __launch_bounds__(256) void gather_kernel(const __half* __restrict__ qkv,
                                                     const __half* __restrict__ vT) {
    const int tid = threadIdx.x;
    int bhg = blockIdx.x >> 2;
    int q = blockIdx.x & 3;
    int b = bhg >> 2, h = 8 + (bhg & 3);
    int s0 = q * 64;
    const __half* kb = qkv + (size_t)b * Sc * E3 + Ec + h * Dc;
    const __half* vr = vT + (size_t)(b * Hc + h) * Dc * Sc;
    __half* Kg = g_Kgh + (size_t)bhg * 256 * 64;
    __half* VgT = g_VgTh + (size_t)bhg * 64 * 256;
    uint4 z = make_uint4(0u, 0u, 0u, 0u);

#pragma unroll
    for (int i = 0; i < 2; i++) {
        int idx = tid + i * 256;
        int sl = idx >> 3, c16 = idx & 7;
        int j = g_gjpad[s0 + sl];
        uint4 kv = (j >= 0) ? *(const uint4*)(kb + (size_t)j * E3 + c16 * 8) : z;
        *(uint4*)(Kg + (size_t)(s0 + sl) * 64 + c16 * 8) = kv;
    }
#pragma unroll
    for (int i = 0; i < 2; i++) {
        int idx = tid + i * 256;
        int d = idx >> 3, sl8 = (idx & 7) * 8;
        uint4 u;
        unsigned short* us = (unsigned short*)&u;
        const __half* vrow = vr + (size_t)d * Sc;
#pragma unroll
        for (int k = 0; k < 8; k++) {
            int j = g_gjpad[s0 + sl8 + k];
            __half val = (j >= 0) ? vrow[j] : __ushort_as_half((unsigned short)0);
            us[k] = *(const unsigned short*)&val;
        }
        *(uint4*)(VgT + (size_t)d * 256 + s0 + sl8) = u;
    }
}

// ---------------------------------------------------------------------------
// fp16 GEMM (m16n8k16), 128x128 tile, 256 threads, BK=64, 2-stage cp.async
// pipeline + ldmatrix. vmode=1 (QKV): bx<12 Q/K natural; bx>=12 V transposed
// into vTp via smem staging. vmode=0 (proj): f32 output.
// ---------------------------------------------------------------------------
#define HST_BYTES 36864      // A 128*144 + B 128*144
#define HST_BOFF  18432
#define HGS_TOTAL (2 * HST_BYTES)

__device__ __forceinline__ void copy_stage_h(const __half* __restrict__ A, const __half* __restrict__ WT,
                                             int m0, int n0, int K, int kt,
                                             uint32_t sbase, int tid) {
    const int kb = kt * 64;
    const uint32_t sA = sbase, sB = sbase + HST_BOFF;
#pragma unroll
    for (int i = 0; i < 4; i++) {
        int idx = tid + i * 256;
        int row = idx >> 3, ch = idx & 7;
        cpa16(sA + row * 144 + ch * 16, A + (size_t)(m0 + row) * K + kb + ch * 8);
    }
#pragma unroll
    for (int i = 0; i < 4; i++) {
        int idx = tid + i * 256;
        int row = idx >> 3, ch = idx & 7;
        cpa16(sB + row * 144 + ch * 16, WT + (size_t)(n0 + row) * K + kb + ch * 8);
    }
    cpa_commit();
}

__global__ __launch_bounds__(256, 2) void gemm_f16(
    const __half* __restrict__ A, const __half* __restrict__ WT,
    const float* __restrict__ bias, float* __restrict__ Cf, __half* __restrict__ Ch,
    __half* __restrict__ vTp, int M, int N, int K, int vmode)
{
    extern __shared__ char smem[];
    const uint32_t sb = smem_u32(smem);

    const int tid = threadIdx.x;
    const int lane = tid & 31;
    const int w = tid >> 5;
    const int g = lane >> 2, c = lane & 3;
    const int wm = (w & 3) * 32;
    const int wn = (w >> 2) * 64;
    const int m0 = blockIdx.y << 7, n0 = blockIdx.x << 7;
    const int NT = K >> 6;

    uint32_t aOff[2], bOff[4];
#pragma unroll
    for (int mt = 0; mt < 2; mt++)
        aOff[mt] = (uint32_t)(wm + mt * 16 + (lane & 15)) * 144 + ((lane >> 4) ? 16u : 0u);
#pragma unroll
    for (int p = 0; p < 4; p++)
        bOff[p] = HST_BOFF +
                  (uint32_t)(wn + 16 * p + ((lane >> 4) & 1) * 8 + (lane & 7)) * 144 +
                  ((lane >> 3) & 1) * 16;

    float acc[2][8][4];
#pragma unroll
    for (int mt = 0; mt < 2; mt++)
#pragma unroll
        for (int nt = 0; nt < 8; nt++)
#pragma unroll
            for (int i = 0; i < 4; i++) acc[mt][nt][i] = 0.f;

    copy_stage_h(A, WT, m0, n0, K, 0, sb, tid);
    copy_stage_h(A, WT, m0, n0, K, 1, sb + HST_BYTES, tid);

    for (int kt = 0; kt < NT; kt++) {
        asm volatile("cp.async.wait_group 1;" ::: "memory");
        __syncthreads();

        const uint32_t stg = sb + (kt & 1) * HST_BYTES;
#pragma unroll
        for (int ks = 0; ks < 4; ks++) {
            const uint32_t ko = ks * 32;
            unsigned a[2][4];
            ldsm4(a[0][0], a[0][1], a[0][2], a[0][3], stg + aOff[0] + ko);
            ldsm4(a[1][0], a[1][1], a[1][2], a[1][3], stg + aOff[1] + ko);
#pragma unroll
            for (int p = 0; p < 4; p++) {
                unsigned b0, b1, b2, b3;
                ldsm4(b0, b1, b2, b3, stg + bOff[p] + ko);
                mma_f16(acc[0][2 * p], a[0], b0, b1);
                mma_f16(acc[1][2 * p], a[1], b0, b1);
                mma_f16(acc[0][2 * p + 1], a[0], b2, b3);
                mma_f16(acc[1][2 * p + 1], a[1], b2, b3);
            }
        }
        __syncthreads();

        if (kt + 2 < NT) copy_stage_h(A, WT, m0, n0, K, kt + 2, sb + (kt & 1) * HST_BYTES, tid);
        else             cpa_commit();
    }

    if (vmode && blockIdx.x >= 12) {
        asm volatile("cp.async.wait_group 0;" ::: "memory");
        __syncthreads();
        __half* st = (__half*)smem;        // [128][136]
#pragma unroll
        for (int mt = 0; mt < 2; mt++) {
            int r = wm + mt * 16 + g;
#pragma unroll
            for (int nt = 0; nt < 8; nt++) {
                int col = wn + nt * 8 + 2 * c;
                float bv0 = bias[n0 + col], bv1 = bias[n0 + col + 1];
                st[col * 136 + r]             = __float2half(acc[mt][nt][0] + bv0);
                st[(col + 1) * 136 + r]       = __float2half(acc[mt][nt][1] + bv1);
                st[col * 136 + r + 8]         = __float2half(acc[mt][nt][2] + bv0);
                st[(col + 1) * 136 + r + 8]   = __float2half(acc[mt][nt][3] + bv1);
            }
        }
        __syncthreads();
        const int b = m0 >> 11, s0r = m0 & (Sc - 1);
#pragma unroll
        for (int i = 0; i < 8; i++) {
            int idx = tid + i * 256;
            int col = idx >> 4, seg = (idx & 15) * 8;
            int colg = n0 + col - 2 * Ec;
            int h = colg >> 6, d = colg & 63;
            uint4 u;
            unsigned short* us = (unsigned short*)&u;
            const unsigned short* srow = (const unsigned short*)(st + col * 136 + seg);
#pragma unroll
            for (int j = 0; j < 8; j++) us[j] = srow[j];
            *(uint4*)(vTp + ((size_t)(b * Hc + h) * Dc + d) * Sc + s0r + seg) = u;
        }
        return;
    }

#pragma unroll
    for (int mt = 0; mt < 2; mt++) {
        int r0 = m0 + wm + mt * 16 + g;
#pragma unroll
        for (int nt = 0; nt < 8; nt++) {
            int col = n0 + wn + nt * 8 + 2 * c;
            float bv0 = bias[col], bv1 = bias[col + 1];
            float v00 = acc[mt][nt][0] + bv0, v01 = acc[mt][nt][1] + bv1;
            float v10 = acc[mt][nt][2] + bv0, v11 = acc[mt][nt][3] + bv1;
            if (vmode) {
                *(__half2*)(Ch + (size_t)r0 * N + col) = __floats2half2_rn(v00, v01);
                *(__half2*)(Ch + (size_t)(r0 + 8) * N + col) = __floats2half2_rn(v10, v11);
            } else {
                *(float2*)(Cf + (size_t)r0 * N + col) = make_float2(v00, v01);
                *(float2*)(Cf + (size_t)(r0 + 8) * N + col) = make_float2(v10, v11);
            }
        }
    }
}

// ---------------------------------------------------------------------------
// fp16 attention (R14): 64 q-rows, 128 threads, log2-domain + ex2.f16x2,
// l via ones-mma, mask fast-paths, LPT grid, ldmatrix, 2-stage cp.async.
// ---------------------------------------------------------------------------
#define AST_BYTES 18432
#define AST_VOFF  9216
#define ATT_TOTAL (2 * AST_BYTES)

__device__ __forceinline__ void attn_issue(
    int it, int n_causal, int n_tiles, int kt_base, int ct0,
    const __half* __restrict__ kb, const __half* __restrict__ vTb,
    const __half* __restrict__ KgB, const __half* __restrict__ VgTB,
    uint32_t sbase, int tid)
{
    if (it >= n_tiles) { cpa_commit(); return; }
    const uint32_t sK = sbase, sV = sbase + AST_VOFF;
    if (it < n_causal) {
        const int k0 = (kt_base + it) << 6;
#pragma unroll
        for (int i = 0; i < 4; i++) {
            int idx = tid + i * 128;
            int slot = idx >> 3, c16 = idx & 7;
            cpa16(sK + slot * 144 + c16 * 16, kb + (size_t)(k0 + slot) * E3 + c16 * 8);
            cpa16(sV + slot * 144 + c16 * 16, vTb + (size_t)slot * Sc + k0 + c16 * 8);
        }
    } else {
        const int ct = ct0 + it - n_causal;
        const __half* Kt = KgB + (size_t)ct * 64 * 64;
#pragma unroll
        for (int i = 0; i < 4; i++) {
            int idx = tid + i * 128;
            int slot = idx >> 3, c16 = idx & 7;
            cpa16(sK + slot * 144 + c16 * 16, Kt + (size_t)slot * 64 + c16 * 8);
            cpa16(sV + slot * 144 + c16 * 16, VgTB + (size_t)slot * 256 + ct * 64 + c16 * 8);
        }
    }
    cpa_commit();
}

__global__ __launch_bounds__(128) void attn_tc(
    const __half* __restrict__ qkv, __half* __restrict__ out, int half_w)
{
    extern __shared__ char smem[];
    const uint32_t sb = smem_u32(smem);

    const int bid = blockIdx.x;
    int b, h, qt;
    if (bid < 512) {
        h = 8 + (bid & 3);
        qt = 31 - ((bid >> 2) & 31);
        b = bid >> 7;
    } else {
        int l = bid - 512;
        h = l & 7;
        qt = 31 - ((l >> 3) & 31);
        b = l >> 8;
    }
    const bool is_local = (h < 8);
    const int q0 = qt << 6;
    const int tid = threadIdx.x;
    const int lane = tid & 31;
    const int w = tid >> 5;
    const int g = lane >> 2, c = lane & 3;

    const __half* qb = qkv + (size_t)b * Sc * E3 + h * Dc;
    const __half* kb = qb + Ec;
    const __half* vTb = g_vTh + (size_t)(b * Hc + h) * Dc * Sc;
    const __half* KgB = g_Kgh + (size_t)(b * 4 + (h - 8)) * 256 * 64;
    const __half* VgTB = g_VgTh + (size_t)(b * 4 + (h - 8)) * 64 * 256;

    const int r0 = q0 + 16 * w + g;
    const int r1 = r0 + 8;

    uint32_t kOff[4], vOff[4];
#pragma unroll
    for (int p = 0; p < 4; p++) {
        uint32_t row = 16 * p + ((lane >> 4) & 1) * 8 + (lane & 7);
        uint32_t co = ((lane >> 3) & 1) * 16;
        kOff[p] = row * 144 + co;
        vOff[p] = AST_VOFF + row * 144 + co;
    }

    __half2 qsch = __half2half2(__float2half(0.18033688f));
    const unsigned qsc = *(unsigned*)&qsch;
    const unsigned* qw0 = (const unsigned*)(qb + (size_t)r0 * E3);
    const unsigned* qw1 = (const unsigned*)(qb + (size_t)r1 * E3);
    unsigned qa[4][4];
#pragma unroll
    for (int ks = 0; ks < 4; ks++) {
        qa[ks][0] = h2mul(qw0[8 * ks + c], qsc);
        qa[ks][1] = h2mul(qw1[8 * ks + c], qsc);
        qa[ks][2] = h2mul(qw0[8 * ks + 4 + c], qsc);
        qa[ks][3] = h2mul(qw1[8 * ks + 4 + c], qsc);
    }

    float o[8][4];
#pragma unroll
    for (int nt = 0; nt < 8; nt++)
#pragma unroll
        for (int i = 0; i < 4; i++) o[nt][i] = 0.f;
    float lacc[4] = {0.f, 0.f, 0.f, 0.f};

    int kt_base, n_causal, n_tiles, ct0 = 0;
    if (is_local) {
        int lo = (q0 - half_w) >> 6;
        kt_base = lo > 0 ? lo : 0;
        n_causal = qt - kt_base + 1;
        n_tiles = n_causal;
    } else {
        kt_base = 0;
        n_causal = qt + 1;
        ct0 = g_gstart[qt] >> 6;
        n_tiles = n_causal + (4 - ct0);
    }

    attn_issue(0, n_causal, n_tiles, kt_base, ct0, kb, vTb, KgB, VgTB, sb, tid);
    attn_issue(1, n_causal, n_tiles, kt_base, ct0, kb, vTb, KgB, VgTB, sb + AST_BYTES, tid);

    for (int it = 0; it < n_tiles; it++) {
        asm volatile("cp.async.wait_group 1;" ::: "memory");
        __syncthreads();

        const uint32_t stg = sb + (it & 1) * AST_BYTES;
        const bool compact = (!is_local) && (it >= n_causal);
        const int kt = kt_base + it;
        const int k0 = kt << 6;
        const int ctb = compact ? (ct0 + it - n_causal) * 64 : 0;

        float s[8][4];
#pragma unroll
        for (int nt = 0; nt < 8; nt++)
#pragma unroll
            for (int i = 0; i < 4; i++) s[nt][i] = 0.f;
#pragma unroll
        for (int ks = 0; ks < 4; ks++) {
            const uint32_t ko = ks * 32;
#pragma unroll
            for (int p = 0; p < 4; p++) {
                unsigned k0f, k1f, k2f, k3f;
                ldsm4(k0f, k1f, k2f, k3f, stg + kOff[p] + ko);
                mma_f16(s[2 * p], qa[ks], k0f, k1f);
                mma_f16(s[2 * p + 1], qa[ks], k2f, k3f);
            }
        }

        int mode = compact ? 3
                 : (kt == qt ? 1
                 : ((is_local && k0 < q0 + 64 - half_w) ? 2 : 0));
        if (mode == 1) {
#pragma unroll
            for (int nt = 0; nt < 8; nt++) {
                int jA = k0 + 8 * nt + 2 * c, jB = jA + 1;
                s[nt][0] = (jA <= r0) ? s[nt][0] : MASKV;
                s[nt][1] = (jB <= r0) ? s[nt][1] : MASKV;
                s[nt][2] = (jA <= r1) ? s[nt][2] : MASKV;
                s[nt][3] = (jB <= r1) ? s[nt][3] : MASKV;
            }
        } else if (mode == 2) {
#pragma unroll
            for (int nt = 0; nt < 8; nt++) {
                int jA = k0 + 8 * nt + 2 * c, jB = jA + 1;
                s[nt][0] = (jA >= r0 - half_w) ? s[nt][0] : MASKV;
                s[nt][1] = (jB >= r0 - half_w) ? s[nt][1] : MASKV;
                s[nt][2] = (jA >= r1 - half_w) ? s[nt][2] : MASKV;
                s[nt][3] = (jB >= r1 - half_w) ? s[nt][3] : MASKV;
            }
        } else if (mode == 3) {
#pragma unroll
            for (int nt = 0; nt < 8; nt++) {
                int jA = g_gjpad[ctb + 8 * nt + 2 * c];
                int jB = g_gjpad[ctb + 8 * nt + 2 * c + 1];
                s[nt][0] = (jA > r0) ? s[nt][0] : MASKV;
                s[nt][1] = (jB > r0) ? s[nt][1] : MASKV;
                s[nt][2] = (jA > r1) ? s[nt][2] : MASKV;
                s[nt][3] = (jB > r1) ? s[nt][3] : MASKV;
            }
        }

        unsigned p01[8], p23[8];
#pragma unroll
        for (int nt = 0; nt < 8; nt++) {
            p01[nt] = ex2h2(packh2(s[nt][0], s[nt][1]));
            p23[nt] = ex2h2(packh2(s[nt][2], s[nt][3]));
        }

#pragma unroll
        for (int t2 = 0; t2 < 4; t2++) {
            unsigned pa[4];
            pa[0] = p01[2 * t2];
            pa[1] = p23[2 * t2];
            pa[2] = p01[2 * t2 + 1];
            pa[3] = p23[2 * t2 + 1];
            mma_f16(lacc, pa, ONES_H2, ONES_H2);
            const uint32_t ko = t2 * 32;
#pragma unroll
            for (int p = 0; p < 4; p++) {
                unsigned v0, v1, v2, v3;
                ldsm4(v0, v1, v2, v3, stg + vOff[p] + ko);
                mma_f16(o[2 * p], pa, v0, v1);
                mma_f16(o[2 * p + 1], pa, v2, v3);
            }
        }
        __syncthreads();

        attn_issue(it + 2, n_causal, n_tiles, kt_base, ct0, kb, vTb, KgB, VgTB,
                   sb + (it & 1) * AST_BYTES, tid);
    }

    float inv0 = 1.0f / lacc[0], inv1 = 1.0f / lacc[2];
    __half* ob0 = out + (size_t)(b * Sc + r0) * Ec + h * Dc;
    __half* ob1 = out + (size_t)(b * Sc + r1) * Ec + h * Dc;
#pragma unroll
    for (int nt = 0; nt < 8; nt++) {
        int d = 8 * nt + 2 * c;
        *(__half2*)(ob0 + d) = __floats2half2_rn(o[nt][0] * inv0, o[nt][1] * inv0);
        *(__half2*)(ob1 + d) = __floats2half2_rn(o[nt][2] * inv1, o[nt][3] * inv1);
    }
}

// ---------------------------------------------------------------------------
extern "C" void kernel_launch(void* const* d_in, const int* in_sizes, int n_in,
                              void* d_out, int out_size) {
    const float* x      = (const float*)d_in[0];
    const float* w_attn = (const float*)d_in[1];
    const float* b_attn = (const float*)d_in[2];
    const float* w_proj = (const float*)d_in[3];
    const float* b_proj = (const float*)d_in[4];
    float* out = (float*)d_out;

    __half *qkvh_p, *attnh_p, *xh_p, *waT_p, *wpT_p, *vT_p;
    cudaGetSymbolAddress((void**)&qkvh_p, g_qkvh);
    cudaGetSymbolAddress((void**)&attnh_p, g_attnh);
    cudaGetSymbolAddress((void**)&xh_p, g_xh);
    cudaGetSymbolAddress((void**)&waT_p, g_waT);
    cudaGetSymbolAddress((void**)&wpT_p, g_wpT);
    cudaGetSymbolAddress((void**)&vT_p, g_vTh);

    int wdw = (int)(128.0 * sqrt((double)Sc / 128.0));
    if (wdw < 32) wdw = 32;
    if (wdw > 512) wdw = 512;
    int half_w = wdw / 2;

    cudaFuncSetAttribute(gemm_f16, cudaFuncAttributeMaxDynamicSharedMemorySize, HGS_TOTAL);
    cudaFuncSetAttribute(attn_tc, cudaFuncAttributeMaxDynamicSharedMemorySize, ATT_TOTAL);

    prep_kernel<<<PREP_BLKS, 256>>>(x, w_attn, w_proj);

    dim3 g1(E3 / 128, (Bc * Sc) / 128);
    gemm_f16<<<g1, 256, HGS_TOTAL>>>(xh_p, waT_p, b_attn, nullptr, qkvh_p, vT_p,
                                     Bc * Sc, E3, Ec, 1);

    gather_kernel<<<64, 256>>>(qkvh_p, vT_p);

    attn_tc<<<1536, 128, ATT_TOTAL>>>(qkvh_p, attnh_p, half_w);

    dim3 g2(Ec / 128, (Bc * Sc) / 128);
    gemm_f16<<<g2, 256, HGS_TOTAL>>>(attnh_p, wpT_p, b_proj, out, nullptr, nullptr,
                                     Bc * Sc, Ec, Ec, 0);
}